// round 3
// baseline (speedup 1.0000x reference)
#include <cuda_runtime.h>
#include <math.h>

#define BSZ 8
#define TT  8192
#define FF  1024
#define HH  256
#define OO  2
#define MTOK (BSZ * TT)   // 65536 tokens

// ---- scratch (static device globals; no runtime allocation) ----
__device__ float g_h[(size_t)MTOK * HH];   // 64 MB: h = relu(bags@W1+b1)
__device__ float g_logit[MTOK];            // per-token attention logits
__device__ float g_slide[BSZ * HH];        // attention-pooled representation

// ============================================================================
// K1: h[M,256] = relu(bags[M,1024] @ W1[1024,256] + b1)
// Classic 128x128x8 tiled SGEMM, 256 threads, 8x8 register blocking.
// ============================================================================
__global__ __launch_bounds__(256, 2)
void k1_gemm_relu(const float* __restrict__ A,      // bags [M, FF]
                  const float* __restrict__ W,      // W1   [FF, HH]
                  const float* __restrict__ bias)   // b1   [HH]
{
    const int N = HH, K = FF;
    __shared__ float As[8][128];
    __shared__ float Bs[8][128];

    const int tid  = threadIdx.x;
    const int tr   = tid >> 4;          // 0..15
    const int tc   = tid & 15;          // 0..15
    const int rowA = tid >> 1;          // 0..127
    const int colA = (tid & 1) << 2;    // 0 or 4
    const int rowB = tid >> 5;          // 0..7
    const int colB = (tid & 31) << 2;   // 0..124

    const float* Ab = A + (size_t)blockIdx.y * 128 * K;
    const float* Wb = W + blockIdx.x * 128;

    float acc[8][8];
    #pragma unroll
    for (int i = 0; i < 8; i++)
        #pragma unroll
        for (int j = 0; j < 8; j++) acc[i][j] = 0.f;

    for (int k0 = 0; k0 < K; k0 += 8) {
        float4 a4 = *reinterpret_cast<const float4*>(Ab + (size_t)rowA * K + k0 + colA);
        As[colA + 0][rowA] = a4.x;
        As[colA + 1][rowA] = a4.y;
        As[colA + 2][rowA] = a4.z;
        As[colA + 3][rowA] = a4.w;
        float4 b4 = *reinterpret_cast<const float4*>(Wb + (size_t)(k0 + rowB) * N + colB);
        *reinterpret_cast<float4*>(&Bs[rowB][colB]) = b4;
        __syncthreads();

        #pragma unroll
        for (int kk = 0; kk < 8; kk++) {
            float rm[8], rn[8];
            #pragma unroll
            for (int i = 0; i < 8; i++) rm[i] = As[kk][tr * 8 + i];
            #pragma unroll
            for (int j = 0; j < 8; j++) rn[j] = Bs[kk][tc * 8 + j];
            #pragma unroll
            for (int i = 0; i < 8; i++)
                #pragma unroll
                for (int j = 0; j < 8; j++)
                    acc[i][j] = fmaf(rm[i], rn[j], acc[i][j]);
        }
        __syncthreads();
    }

    const int r0 = blockIdx.y * 128 + tr * 8;
    const int c0 = blockIdx.x * 128 + tc * 8;
    #pragma unroll
    for (int i = 0; i < 8; i++) {
        #pragma unroll
        for (int j4 = 0; j4 < 8; j4 += 4) {
            float4 o;
            float v0 = acc[i][j4 + 0] + bias[c0 + j4 + 0];
            float v1 = acc[i][j4 + 1] + bias[c0 + j4 + 1];
            float v2 = acc[i][j4 + 2] + bias[c0 + j4 + 2];
            float v3 = acc[i][j4 + 3] + bias[c0 + j4 + 3];
            o.x = v0 > 0.f ? v0 : 0.f;
            o.y = v1 > 0.f ? v1 : 0.f;
            o.z = v2 > 0.f ? v2 : 0.f;
            o.w = v3 > 0.f ? v3 : 0.f;
            *reinterpret_cast<float4*>(&g_h[(size_t)(r0 + i) * N + c0 + j4]) = o;
        }
    }
}

// ============================================================================
// K2: per-token gated-attention logit.
//   logit[m] = sum_c tanh(h[m,:]@Wv[:,c]+bv[c]) * sigmoid(h[m,:]@Wu[:,c]+bu[c]) * ww[c] + bw
// Dual GEMM (64 tokens x 64 cols x K=256 tiles), deterministic smem reduction.
// ============================================================================
__global__ __launch_bounds__(256)
void k2_gates(const float* __restrict__ Wv, const float* __restrict__ bv,
              const float* __restrict__ Wu, const float* __restrict__ bu,
              const float* __restrict__ ww, const float* __restrict__ bw,
              const unsigned char* __restrict__ mask)
{
    __shared__ float As[16][64];
    __shared__ float BsV[16][64];
    __shared__ float BsU[16][64];
    __shared__ float red[64][17];     // +1 pad: conflict-free column reduce
    __shared__ float outacc[64];

    const int tid  = threadIdx.x;
    const int tr   = tid >> 4;          // 0..15
    const int tc   = tid & 15;          // 0..15
    const int rowA = tid >> 2;          // 0..63
    const int colA = (tid & 3) << 2;    // 0..12
    const int rowB = tid >> 4;          // 0..15
    const int colB = (tid & 15) << 2;   // 0..60
    const size_t m0 = (size_t)blockIdx.x * 64;

    if (tid < 64) outacc[tid] = 0.f;
    __syncthreads();

    for (int nb = 0; nb < 4; ++nb) {
        const int n0 = nb * 64;
        float accV[4][4], accU[4][4];
        #pragma unroll
        for (int i = 0; i < 4; i++)
            #pragma unroll
            for (int j = 0; j < 4; j++) { accV[i][j] = 0.f; accU[i][j] = 0.f; }

        for (int k0 = 0; k0 < HH; k0 += 16) {
            float4 a4 = *reinterpret_cast<const float4*>(&g_h[(m0 + rowA) * HH + k0 + colA]);
            As[colA + 0][rowA] = a4.x;
            As[colA + 1][rowA] = a4.y;
            As[colA + 2][rowA] = a4.z;
            As[colA + 3][rowA] = a4.w;
            float4 v4 = *reinterpret_cast<const float4*>(Wv + (size_t)(k0 + rowB) * HH + n0 + colB);
            *reinterpret_cast<float4*>(&BsV[rowB][colB]) = v4;
            float4 u4 = *reinterpret_cast<const float4*>(Wu + (size_t)(k0 + rowB) * HH + n0 + colB);
            *reinterpret_cast<float4*>(&BsU[rowB][colB]) = u4;
            __syncthreads();

            #pragma unroll
            for (int kk = 0; kk < 16; kk++) {
                float rm[4], rv[4], ru[4];
                #pragma unroll
                for (int i = 0; i < 4; i++) rm[i] = As[kk][tr * 4 + i];
                #pragma unroll
                for (int j = 0; j < 4; j++) { rv[j] = BsV[kk][tc * 4 + j]; ru[j] = BsU[kk][tc * 4 + j]; }
                #pragma unroll
                for (int i = 0; i < 4; i++)
                    #pragma unroll
                    for (int j = 0; j < 4; j++) {
                        accV[i][j] = fmaf(rm[i], rv[j], accV[i][j]);
                        accU[i][j] = fmaf(rm[i], ru[j], accU[i][j]);
                    }
            }
            __syncthreads();
        }

        float rowsum[4] = {0.f, 0.f, 0.f, 0.f};
        #pragma unroll
        for (int j = 0; j < 4; j++) {
            const int c = n0 + tc * 4 + j;
            const float wj = ww[c], bvj = bv[c], buj = bu[c];
            #pragma unroll
            for (int i = 0; i < 4; i++) {
                float v = tanhf(accV[i][j] + bvj);
                float u = 1.f / (1.f + expf(-(accU[i][j] + buj)));
                rowsum[i] = fmaf(v * u, wj, rowsum[i]);
            }
        }
        #pragma unroll
        for (int i = 0; i < 4; i++) red[tr * 4 + i][tc] = rowsum[i];
        __syncthreads();
        if (tid < 64) {
            float s = 0.f;
            #pragma unroll
            for (int c = 0; c < 16; c++) s += red[tid][c];
            outacc[tid] += s;               // single writer per row -> deterministic
        }
        __syncthreads();
    }

    if (tid < 64) {
        const size_t m = m0 + tid;
        float val = outacc[tid] + bw[0];
        if (mask[m]) val = -1e30f;
        g_logit[m] = val;
    }
}

// ============================================================================
// K3: per-batch softmax over T + attention-weighted pooling of h.
//   slide[b,:] = sum_t softmax(logit[b,:])_t * h[b,t,:]
// One CTA (1024 threads) per batch.
// ============================================================================
__global__ __launch_bounds__(1024)
void k3_softmax_agg()
{
    __shared__ float sred[1024];
    __shared__ float wsh[1024];
    __shared__ float bcast[2];

    const int b = blockIdx.x, tid = threadIdx.x;
    const float* lg = g_logit + (size_t)b * TT;

    // --- max ---
    float lmax = -3.4e38f;
    #pragma unroll
    for (int i = 0; i < 8; i++) lmax = fmaxf(lmax, lg[tid + i * 1024]);
    sred[tid] = lmax;
    __syncthreads();
    for (int s = 512; s > 0; s >>= 1) {
        if (tid < s) sred[tid] = fmaxf(sred[tid], sred[tid + s]);
        __syncthreads();
    }
    if (tid == 0) bcast[0] = sred[0];
    __syncthreads();
    const float mx = bcast[0];

    // --- sum exp ---
    float lsum = 0.f;
    #pragma unroll
    for (int i = 0; i < 8; i++) lsum += expf(lg[tid + i * 1024] - mx);
    sred[tid] = lsum;
    __syncthreads();
    for (int s = 512; s > 0; s >>= 1) {
        if (tid < s) sred[tid] += sred[tid + s];
        __syncthreads();
    }
    if (tid == 0) bcast[1] = 1.f / sred[0];
    __syncthreads();
    const float inv = bcast[1];

    // --- weighted aggregation: 4 t-groups x 256 h-columns ---
    const int hc = tid & 255, grp = tid >> 8;
    float acc = 0.f;
    for (int t0 = 0; t0 < TT; t0 += 1024) {
        wsh[tid] = expf(lg[t0 + tid] - mx) * inv;
        __syncthreads();
        for (int tt = grp; tt < 1024; tt += 4)
            acc = fmaf(wsh[tt], g_h[((size_t)b * TT + t0 + tt) * HH + hc], acc);
        __syncthreads();
    }
    sred[tid] = acc;
    __syncthreads();
    if (tid < 256)
        g_slide[b * HH + tid] = sred[tid] + sred[256 + tid] + sred[512 + tid] + sred[768 + tid];
}

// ============================================================================
// K4: logits[b,o] = slide[b,:] @ Wc[:,o] + bc[o]   (16 warp-reduced dots)
// ============================================================================
__global__ __launch_bounds__(512)
void k4_final(const float* __restrict__ Wc, const float* __restrict__ bc,
              float* __restrict__ out)
{
    const int tid  = threadIdx.x;
    const int pair = tid >> 5;       // 0..15
    const int lane = tid & 31;
    const int b = pair >> 1, o = pair & 1;
    float s = 0.f;
    for (int j = lane; j < HH; j += 32)
        s = fmaf(g_slide[b * HH + j], Wc[j * OO + o], s);
    #pragma unroll
    for (int off = 16; off > 0; off >>= 1) s += __shfl_down_sync(0xffffffffu, s, off);
    if (lane == 0) out[b * OO + o] = s + bc[o];
}

// ============================================================================
extern "C" void kernel_launch(void* const* d_in, const int* in_sizes, int n_in,
                              void* d_out, int out_size)
{
    const float*         bags = (const float*)d_in[0];
    const unsigned char* mask = (const unsigned char*)d_in[1];
    const float*         W1   = (const float*)d_in[2];
    const float*         b1   = (const float*)d_in[3];
    const float*         Wv   = (const float*)d_in[4];
    const float*         bv   = (const float*)d_in[5];
    const float*         Wu   = (const float*)d_in[6];
    const float*         bu   = (const float*)d_in[7];
    const float*         ww   = (const float*)d_in[8];
    const float*         bw   = (const float*)d_in[9];
    const float*         Wc   = (const float*)d_in[10];
    const float*         bc   = (const float*)d_in[11];
    float*               out  = (float*)d_out;

    k1_gemm_relu<<<dim3(HH / 128, MTOK / 128), 256>>>(bags, W1, b1);
    k2_gates<<<MTOK / 64, 256>>>(Wv, bv, Wu, bu, ww, bw, mask);
    k3_softmax_agg<<<BSZ, 1024>>>();
    k4_final<<<1, 512>>>(Wc, bc, out);
}

// round 4
// speedup vs baseline: 2.8420x; 2.8420x over previous
#include <cuda_runtime.h>
#include <math.h>
#include <stdint.h>
#include <float.h>

#define BSZ 8
#define TT  8192
#define FF  1024
#define HH  256
#define OO  2
#define MTOK (BSZ * TT)   // 65536 tokens

// ---- scratch (static device globals; no runtime allocation) ----
__device__ float  g_h[(size_t)MTOK * HH];   // 64 MB
__device__ float  g_logit[MTOK];
__device__ float2 g_stat[BSZ];              // {max, 1/sumexp}
__device__ float  g_part[BSZ * 32 * HH];    // partial pooled sums
__device__ float  g_slide[BSZ * HH];

// ---- helpers ----
__device__ __forceinline__ uint32_t f2tf(float f) {
    uint32_t r; asm("cvt.rna.tf32.f32 %0, %1;" : "=r"(r) : "f"(f)); return r;
}
__device__ __forceinline__ float tanhfast(float x) {
    float y; asm("tanh.approx.f32 %0, %1;" : "=f"(y) : "f"(x)); return y;
}
// D += A(16x8) * B(8x8), tf32 inputs, fp32 accumulate
__device__ __forceinline__ void mma8(float4& d, const uint32_t* a, uint32_t b0, uint32_t b1) {
    asm volatile("mma.sync.aligned.m16n8k8.row.col.f32.tf32.tf32.f32 "
        "{%0,%1,%2,%3}, {%4,%5,%6,%7}, {%8,%9}, {%0,%1,%2,%3};"
        : "+f"(d.x), "+f"(d.y), "+f"(d.z), "+f"(d.w)
        : "r"(a[0]), "r"(a[1]), "r"(a[2]), "r"(a[3]), "r"(b0), "r"(b1));
}

// ============================================================================
// K1: h = relu(bags[M,1024] @ W1[1024,256] + b1)   — tf32 MMA, CTA 128x128x16,
// 8 warps (warp tile 32x64), double-buffered smem + register prefetch.
// ============================================================================
#define LDA1 136   // pad so (8k+m) mod 32 is unique -> conflict-free frag LDS
__global__ __launch_bounds__(256, 2)
void k1_gemm_relu(const float* __restrict__ A, const float* __restrict__ W,
                  const float* __restrict__ bias)
{
    __shared__ uint32_t As[2][16][LDA1];   // [k][m], tf32 bits
    __shared__ uint32_t Bs[2][16][LDA1];   // [k][n]

    const int tid = threadIdx.x;
    const int lane = tid & 31, wid = tid >> 5;
    const int wm = wid & 3, wn = wid >> 2;    // warp tile: rows wm*32, cols wn*64
    const int g = lane >> 2, tg = lane & 3;

    const size_t mBase = (size_t)blockIdx.y * 128;
    const int    nBase = blockIdx.x * 128;

    const int am = tid >> 1, ak = (tid & 1) << 3;     // A: row am, k-offset ak (8 floats)
    const int bk = tid >> 4, bn = (tid & 15) << 3;    // B: k-row bk, n-offset bn (8 floats)

    const float* aP = A + (mBase + am) * FF + ak;
    const float* bP = W + (size_t)bk * HH + nBase + bn;

    float4 acc[2][8];
    #pragma unroll
    for (int i = 0; i < 2; i++)
        #pragma unroll
        for (int j = 0; j < 8; j++) acc[i][j] = make_float4(0.f, 0.f, 0.f, 0.f);

    float4 ra0, ra1, rb0, rb1;
    ra0 = *(const float4*)(aP);     ra1 = *(const float4*)(aP + 4);
    rb0 = *(const float4*)(bP);     rb1 = *(const float4*)(bP + 4);

    auto store_tile = [&](int p) {
        As[p][ak + 0][am] = f2tf(ra0.x); As[p][ak + 1][am] = f2tf(ra0.y);
        As[p][ak + 2][am] = f2tf(ra0.z); As[p][ak + 3][am] = f2tf(ra0.w);
        As[p][ak + 4][am] = f2tf(ra1.x); As[p][ak + 5][am] = f2tf(ra1.y);
        As[p][ak + 6][am] = f2tf(ra1.z); As[p][ak + 7][am] = f2tf(ra1.w);
        uint4 t0 = make_uint4(f2tf(rb0.x), f2tf(rb0.y), f2tf(rb0.z), f2tf(rb0.w));
        uint4 t1 = make_uint4(f2tf(rb1.x), f2tf(rb1.y), f2tf(rb1.z), f2tf(rb1.w));
        *(uint4*)&Bs[p][bk][bn]     = t0;
        *(uint4*)&Bs[p][bk][bn + 4] = t1;
    };

    store_tile(0);
    __syncthreads();

    const int KT = FF / 16;   // 64
    for (int kt = 0; kt < KT; kt++) {
        const int p = kt & 1;
        if (kt + 1 < KT) {
            const float* ap = aP + (kt + 1) * 16;
            const float* bp = bP + (size_t)(kt + 1) * 16 * HH;
            ra0 = *(const float4*)(ap);     ra1 = *(const float4*)(ap + 4);
            rb0 = *(const float4*)(bp);     rb1 = *(const float4*)(bp + 4);
        }
        #pragma unroll
        for (int ks = 0; ks < 2; ks++) {
            const int k0 = ks * 8 + tg;
            uint32_t afr[2][4];
            #pragma unroll
            for (int fm = 0; fm < 2; fm++) {
                const int m = wm * 32 + fm * 16 + g;
                afr[fm][0] = As[p][k0][m];     afr[fm][1] = As[p][k0][m + 8];
                afr[fm][2] = As[p][k0 + 4][m]; afr[fm][3] = As[p][k0 + 4][m + 8];
            }
            #pragma unroll
            for (int fn = 0; fn < 8; fn++) {
                const int n = wn * 64 + fn * 8 + g;
                const uint32_t b0 = Bs[p][k0][n], b1 = Bs[p][k0 + 4][n];
                mma8(acc[0][fn], afr[0], b0, b1);
                mma8(acc[1][fn], afr[1], b0, b1);
            }
        }
        if (kt + 1 < KT) {
            store_tile(p ^ 1);
            __syncthreads();
        }
    }

    // epilogue: bias + relu, two float2 stores per fragment
    #pragma unroll
    for (int fm = 0; fm < 2; fm++) {
        const size_t m = mBase + wm * 32 + fm * 16 + g;
        #pragma unroll
        for (int fn = 0; fn < 8; fn++) {
            const int n = nBase + wn * 64 + fn * 8 + tg * 2;
            const float bb0 = bias[n], bb1 = bias[n + 1];
            float2 r0, r1;
            r0.x = fmaxf(acc[fm][fn].x + bb0, 0.f);
            r0.y = fmaxf(acc[fm][fn].y + bb1, 0.f);
            r1.x = fmaxf(acc[fm][fn].z + bb0, 0.f);
            r1.y = fmaxf(acc[fm][fn].w + bb1, 0.f);
            *(float2*)&g_h[m * HH + n]       = r0;
            *(float2*)&g_h[(m + 8) * HH + n] = r1;
        }
    }
}

// ============================================================================
// K2: gated-attention logits. Dual tf32 MMA (V and U share A=h), CTA 128 tokens,
// 4 n-blocks of 64 cols, warp tile 32x32. Nonlinearity via MUFU.TANH
// (sigmoid(x) = 0.5*tanh(x/2)+0.5 — exact identity). Deterministic reduce.
// ============================================================================
#define LDA2 136
#define LDB2 72
__global__ __launch_bounds__(256, 2)
void k2_gates(const float* __restrict__ Wv, const float* __restrict__ bv,
              const float* __restrict__ Wu, const float* __restrict__ bu,
              const float* __restrict__ ww, const float* __restrict__ bw,
              const unsigned char* __restrict__ mask)
{
    __shared__ uint32_t As[2][16][LDA2];
    __shared__ uint32_t BV[2][16][LDB2];
    __shared__ uint32_t BU[2][16][LDB2];
    __shared__ float red[2][128];

    const int tid = threadIdx.x;
    const int lane = tid & 31, wid = tid >> 5;
    const int wm = wid & 3, wn = wid >> 2;    // warp: rows wm*32, cols wn*32
    const int g = lane >> 2, tg = lane & 3;
    const size_t m0 = (size_t)blockIdx.x * 128;

    const int am = tid >> 1, ak = (tid & 1) << 3;
    const int bk = tid >> 4, bn = (tid & 15) << 2;   // B tiles 16x64 -> 1 float4/thread

    float rowsum[4] = {0.f, 0.f, 0.f, 0.f};

    for (int nb = 0; nb < 4; nb++) {
        const int n0 = nb * 64;
        float4 accV[2][4], accU[2][4];
        #pragma unroll
        for (int i = 0; i < 2; i++)
            #pragma unroll
            for (int j = 0; j < 4; j++) {
                accV[i][j] = make_float4(0.f, 0.f, 0.f, 0.f);
                accU[i][j] = make_float4(0.f, 0.f, 0.f, 0.f);
            }

        float4 ra0, ra1, rv, ru;
        auto load_tile = [&](int kt) {
            const float* ap = &g_h[(m0 + am) * HH + kt * 16 + ak];
            ra0 = *(const float4*)(ap);  ra1 = *(const float4*)(ap + 4);
            const size_t bo = (size_t)(kt * 16 + bk) * HH + n0 + bn;
            rv = *(const float4*)(Wv + bo);
            ru = *(const float4*)(Wu + bo);
        };
        auto store_tile = [&](int p) {
            As[p][ak + 0][am] = f2tf(ra0.x); As[p][ak + 1][am] = f2tf(ra0.y);
            As[p][ak + 2][am] = f2tf(ra0.z); As[p][ak + 3][am] = f2tf(ra0.w);
            As[p][ak + 4][am] = f2tf(ra1.x); As[p][ak + 5][am] = f2tf(ra1.y);
            As[p][ak + 6][am] = f2tf(ra1.z); As[p][ak + 7][am] = f2tf(ra1.w);
            *(uint4*)&BV[p][bk][bn] = make_uint4(f2tf(rv.x), f2tf(rv.y), f2tf(rv.z), f2tf(rv.w));
            *(uint4*)&BU[p][bk][bn] = make_uint4(f2tf(ru.x), f2tf(ru.y), f2tf(ru.z), f2tf(ru.w));
        };

        load_tile(0); store_tile(0);
        __syncthreads();

        for (int kt = 0; kt < 16; kt++) {
            const int p = kt & 1;
            if (kt + 1 < 16) load_tile(kt + 1);
            #pragma unroll
            for (int ks = 0; ks < 2; ks++) {
                const int k0 = ks * 8 + tg;
                uint32_t afr[2][4];
                #pragma unroll
                for (int fm = 0; fm < 2; fm++) {
                    const int m = wm * 32 + fm * 16 + g;
                    afr[fm][0] = As[p][k0][m];     afr[fm][1] = As[p][k0][m + 8];
                    afr[fm][2] = As[p][k0 + 4][m]; afr[fm][3] = As[p][k0 + 4][m + 8];
                }
                #pragma unroll
                for (int fn = 0; fn < 4; fn++) {
                    const int n = wn * 32 + fn * 8 + g;
                    const uint32_t v0 = BV[p][k0][n], v1 = BV[p][k0 + 4][n];
                    const uint32_t u0 = BU[p][k0][n], u1 = BU[p][k0 + 4][n];
                    mma8(accV[0][fn], afr[0], v0, v1);
                    mma8(accV[1][fn], afr[1], v0, v1);
                    mma8(accU[0][fn], afr[0], u0, u1);
                    mma8(accU[1][fn], afr[1], u0, u1);
                }
            }
            if (kt + 1 < 16) {
                store_tile(p ^ 1);
                __syncthreads();
            }
        }
        __syncthreads();   // safe to overwrite smem next nb

        // nonlinearity + weighted column reduce into per-row accumulators
        #pragma unroll
        for (int fm = 0; fm < 2; fm++) {
            #pragma unroll
            for (int fn = 0; fn < 4; fn++) {
                const int c = n0 + wn * 32 + fn * 8 + tg * 2;
                const float bv0 = bv[c], bv1 = bv[c + 1];
                const float bu0 = bu[c], bu1 = bu[c + 1];
                const float w0 = ww[c],  w1 = ww[c + 1];
                const float4 av = accV[fm][fn], au = accU[fm][fn];
                float v, u;
                v = tanhfast(av.x + bv0); u = 0.5f * tanhfast(0.5f * (au.x + bu0)) + 0.5f;
                rowsum[fm * 2 + 0] = fmaf(v * u, w0, rowsum[fm * 2 + 0]);
                v = tanhfast(av.y + bv1); u = 0.5f * tanhfast(0.5f * (au.y + bu1)) + 0.5f;
                rowsum[fm * 2 + 0] = fmaf(v * u, w1, rowsum[fm * 2 + 0]);
                v = tanhfast(av.z + bv0); u = 0.5f * tanhfast(0.5f * (au.z + bu0)) + 0.5f;
                rowsum[fm * 2 + 1] = fmaf(v * u, w0, rowsum[fm * 2 + 1]);
                v = tanhfast(av.w + bv1); u = 0.5f * tanhfast(0.5f * (au.w + bu1)) + 0.5f;
                rowsum[fm * 2 + 1] = fmaf(v * u, w1, rowsum[fm * 2 + 1]);
            }
        }
    }

    // reduce the 4 column-subsets (lanes sharing g) -> full row sums
    #pragma unroll
    for (int o = 1; o <= 2; o <<= 1)
        #pragma unroll
        for (int i = 0; i < 4; i++)
            rowsum[i] += __shfl_xor_sync(0xffffffffu, rowsum[i], o);

    if (tg == 0) {
        #pragma unroll
        for (int i = 0; i < 4; i++)
            red[wn][wm * 32 + (i >> 1) * 16 + (i & 1) * 8 + g] = rowsum[i];
    }
    __syncthreads();
    if (tid < 128) {
        const size_t m = m0 + tid;
        float val = red[0][tid] + red[1][tid] + bw[0];
        if (mask[m]) val = -1e30f;
        g_logit[m] = val;
    }
}

// ============================================================================
// K3a: per-batch softmax stats (max, 1/sumexp). 8 CTAs x 1024 threads.
// ============================================================================
__global__ __launch_bounds__(1024)
void k3a_stats()
{
    __shared__ float sred[1024];
    const int b = blockIdx.x, tid = threadIdx.x;
    const float* lg = g_logit + (size_t)b * TT;

    float lmax = -FLT_MAX;
    #pragma unroll
    for (int i = 0; i < 8; i++) lmax = fmaxf(lmax, lg[tid + i * 1024]);
    sred[tid] = lmax;
    __syncthreads();
    for (int s = 512; s > 0; s >>= 1) {
        if (tid < s) sred[tid] = fmaxf(sred[tid], sred[tid + s]);
        __syncthreads();
    }
    const float mx = sred[0];
    __syncthreads();

    float lsum = 0.f;
    #pragma unroll
    for (int i = 0; i < 8; i++) lsum += expf(lg[tid + i * 1024] - mx);
    sred[tid] = lsum;
    __syncthreads();
    for (int s = 512; s > 0; s >>= 1) {
        if (tid < s) sred[tid] += sred[tid + s];
        __syncthreads();
    }
    if (tid == 0) g_stat[b] = make_float2(mx, 1.f / sred[0]);
}

// ============================================================================
// K3b: partial attention-weighted pooling. grid (32 chunks, 8 batches) x 256.
// ============================================================================
__global__ __launch_bounds__(256)
void k3b_pool()
{
    __shared__ float w[256];
    const int b = blockIdx.y, ch = blockIdx.x, tid = threadIdx.x;
    const float2 st = g_stat[b];
    const int t0 = ch * 256;

    w[tid] = expf(g_logit[(size_t)b * TT + t0 + tid] - st.x) * st.y;
    __syncthreads();

    const float* hp = &g_h[((size_t)b * TT + t0) * HH + tid];
    float a0 = 0.f, a1 = 0.f, a2 = 0.f, a3 = 0.f;
    for (int t = 0; t < 256; t += 4) {
        a0 = fmaf(w[t + 0], hp[(size_t)(t + 0) * HH], a0);
        a1 = fmaf(w[t + 1], hp[(size_t)(t + 1) * HH], a1);
        a2 = fmaf(w[t + 2], hp[(size_t)(t + 2) * HH], a2);
        a3 = fmaf(w[t + 3], hp[(size_t)(t + 3) * HH], a3);
    }
    g_part[((size_t)b * 32 + ch) * HH + tid] = (a0 + a1) + (a2 + a3);
}

// ============================================================================
// K3c: reduce 32 chunk-partials -> slide repr. 8 CTAs x 256 threads.
// ============================================================================
__global__ __launch_bounds__(256)
void k3c_reduce()
{
    const int b = blockIdx.x, c = threadIdx.x;
    float s = 0.f;
    #pragma unroll 8
    for (int j = 0; j < 32; j++) s += g_part[((size_t)b * 32 + j) * HH + c];
    g_slide[b * HH + c] = s;
}

// ============================================================================
// K4: logits[b,o] = slide[b,:] @ Wc[:,o] + bc[o]
// ============================================================================
__global__ __launch_bounds__(512)
void k4_final(const float* __restrict__ Wc, const float* __restrict__ bc,
              float* __restrict__ out)
{
    const int tid = threadIdx.x;
    const int pair = tid >> 5, lane = tid & 31;
    const int b = pair >> 1, o = pair & 1;
    float s = 0.f;
    for (int j = lane; j < HH; j += 32)
        s = fmaf(g_slide[b * HH + j], Wc[j * OO + o], s);
    #pragma unroll
    for (int off = 16; off > 0; off >>= 1) s += __shfl_down_sync(0xffffffffu, s, off);
    if (lane == 0) out[b * OO + o] = s + bc[o];
}

// ============================================================================
extern "C" void kernel_launch(void* const* d_in, const int* in_sizes, int n_in,
                              void* d_out, int out_size)
{
    const float*         bags = (const float*)d_in[0];
    const unsigned char* mask = (const unsigned char*)d_in[1];
    const float*         W1   = (const float*)d_in[2];
    const float*         b1   = (const float*)d_in[3];
    const float*         Wv   = (const float*)d_in[4];
    const float*         bv   = (const float*)d_in[5];
    const float*         Wu   = (const float*)d_in[6];
    const float*         bu   = (const float*)d_in[7];
    const float*         ww   = (const float*)d_in[8];
    const float*         bw   = (const float*)d_in[9];
    const float*         Wc   = (const float*)d_in[10];
    const float*         bc   = (const float*)d_in[11];
    float*               out  = (float*)d_out;

    k1_gemm_relu<<<dim3(HH / 128, MTOK / 128), 256>>>(bags, W1, b1);
    k2_gates<<<MTOK / 128, 256>>>(Wv, bv, Wu, bu, ww, bw, mask);
    k3a_stats<<<BSZ, 1024>>>();
    k3b_pool<<<dim3(32, BSZ), 256>>>();
    k3c_reduce<<<BSZ, 256>>>();
    k4_final<<<1, 512>>>(Wc, bc, out);
}

// round 5
// speedup vs baseline: 3.9008x; 1.3726x over previous
#include <cuda_runtime.h>
#include <math.h>
#include <stdint.h>
#include <float.h>

#define BSZ 8
#define TT  8192
#define FF  1024
#define HH  256
#define OO  2
#define MTOK (BSZ * TT)   // 65536 tokens
#define NCHUNK 64         // k3b token chunks per batch (128 tokens each)

// ---- scratch (static device globals; no runtime allocation) ----
__device__ float  g_h[(size_t)MTOK * HH];   // 64 MB
__device__ float  g_logit[MTOK];
__device__ float2 g_stat[BSZ];              // {max, 1/sumexp}
__device__ float  g_part[BSZ * NCHUNK * HH];
__device__ float  g_slide[BSZ * HH];

// ---- helpers ----
// pack two fp32 -> bf16x2 (lo = first/even-k element, hi = second/odd-k)
__device__ __forceinline__ uint32_t pbf(float lo, float hi) {
    uint32_t r; asm("cvt.rn.bf16x2.f32 %0, %1, %2;" : "=r"(r) : "f"(hi), "f"(lo)); return r;
}
__device__ __forceinline__ float tanhfast(float x) {
    float y; asm("tanh.approx.f32 %0, %1;" : "=f"(y) : "f"(x)); return y;
}
// D += A(16x16) * B(16x8), bf16 inputs, fp32 accumulate
__device__ __forceinline__ void mma16(float4& d, const uint32_t* a, uint32_t b0, uint32_t b1) {
    asm volatile("mma.sync.aligned.m16n8k16.row.col.f32.bf16.bf16.f32 "
        "{%0,%1,%2,%3}, {%4,%5,%6,%7}, {%8,%9}, {%0,%1,%2,%3};"
        : "+f"(d.x), "+f"(d.y), "+f"(d.z), "+f"(d.w)
        : "r"(a[0]), "r"(a[1]), "r"(a[2]), "r"(a[3]), "r"(b0), "r"(b1));
}

// ============================================================================
// K1: h = relu(bags[M,1024] @ W1[1024,256] + b1) — bf16 MMA m16n8k16,
// CTA 128x128x16, 8 warps (warp tile 32x64), double-buffered smem.
// Smem holds bf16x2 packed along k: As[kpair][m], Bs[kpair][n].
// ============================================================================
#define LDA1 136   // pad: bank = kpair*8 + g -> conflict-free fragment LDS
__global__ __launch_bounds__(256, 2)
void k1_gemm_relu(const float* __restrict__ A, const float* __restrict__ W,
                  const float* __restrict__ bias)
{
    __shared__ uint32_t As[2][8][LDA1];   // [k/2][m]
    __shared__ uint32_t Bs[2][8][LDA1];   // [k/2][n]

    const int tid = threadIdx.x;
    const int lane = tid & 31, wid = tid >> 5;
    const int wm = wid & 3, wn = wid >> 2;    // warp tile rows wm*32, cols wn*64
    const int g = lane >> 2, tg = lane & 3;

    const size_t mBase = (size_t)blockIdx.y * 128;
    const int    nBase = blockIdx.x * 128;

    const int am = tid >> 1, ak = (tid & 1) << 3;     // A: row am, k-offset ak
    const int bk = (tid >> 5) << 1;                   // B: k-rows bk, bk+1
    const int bn = (tid & 31) << 2;                   // 4 n-values

    const float* aP = A + (mBase + am) * FF + ak;
    const float* bP = W + (size_t)bk * HH + nBase + bn;

    float4 acc[2][8];
    #pragma unroll
    for (int i = 0; i < 2; i++)
        #pragma unroll
        for (int j = 0; j < 8; j++) acc[i][j] = make_float4(0.f, 0.f, 0.f, 0.f);

    float4 ra0, ra1, rb0, rb1;
    ra0 = *(const float4*)(aP);       ra1 = *(const float4*)(aP + 4);
    rb0 = *(const float4*)(bP);       rb1 = *(const float4*)(bP + HH);

    auto store_tile = [&](int p) {
        const int a2 = ak >> 1;
        As[p][a2 + 0][am] = pbf(ra0.x, ra0.y);
        As[p][a2 + 1][am] = pbf(ra0.z, ra0.w);
        As[p][a2 + 2][am] = pbf(ra1.x, ra1.y);
        As[p][a2 + 3][am] = pbf(ra1.z, ra1.w);
        uint4 t = make_uint4(pbf(rb0.x, rb1.x), pbf(rb0.y, rb1.y),
                             pbf(rb0.z, rb1.z), pbf(rb0.w, rb1.w));
        *(uint4*)&Bs[p][bk >> 1][bn] = t;
    };

    store_tile(0);
    __syncthreads();

    const int KT = FF / 16;   // 64
    for (int kt = 0; kt < KT; kt++) {
        const int p = kt & 1;
        if (kt + 1 < KT) {
            const float* ap = aP + (kt + 1) * 16;
            const float* bp = bP + (size_t)(kt + 1) * 16 * HH;
            ra0 = *(const float4*)(ap);      ra1 = *(const float4*)(ap + 4);
            rb0 = *(const float4*)(bp);      rb1 = *(const float4*)(bp + HH);
        }
        uint32_t afr[2][4];
        #pragma unroll
        for (int fm = 0; fm < 2; fm++) {
            const int m = wm * 32 + fm * 16 + g;
            afr[fm][0] = As[p][tg][m];     afr[fm][1] = As[p][tg][m + 8];
            afr[fm][2] = As[p][tg + 4][m]; afr[fm][3] = As[p][tg + 4][m + 8];
        }
        #pragma unroll
        for (int fn = 0; fn < 8; fn++) {
            const int n = wn * 64 + fn * 8 + g;
            const uint32_t b0 = Bs[p][tg][n], b1 = Bs[p][tg + 4][n];
            mma16(acc[0][fn], afr[0], b0, b1);
            mma16(acc[1][fn], afr[1], b0, b1);
        }
        if (kt + 1 < KT) {
            store_tile(p ^ 1);
            __syncthreads();
        }
    }

    #pragma unroll
    for (int fm = 0; fm < 2; fm++) {
        const size_t m = mBase + wm * 32 + fm * 16 + g;
        #pragma unroll
        for (int fn = 0; fn < 8; fn++) {
            const int n = nBase + wn * 64 + fn * 8 + tg * 2;
            const float bb0 = bias[n], bb1 = bias[n + 1];
            float2 r0, r1;
            r0.x = fmaxf(acc[fm][fn].x + bb0, 0.f);
            r0.y = fmaxf(acc[fm][fn].y + bb1, 0.f);
            r1.x = fmaxf(acc[fm][fn].z + bb0, 0.f);
            r1.y = fmaxf(acc[fm][fn].w + bb1, 0.f);
            *(float2*)&g_h[m * HH + n]       = r0;
            *(float2*)&g_h[(m + 8) * HH + n] = r1;
        }
    }
}

// ============================================================================
// K2: gated-attention logits via dual bf16 MMA (V,U share A=h).
// CTA = 128 tokens, 4 n-blocks of 64 cols, warp tile 32x32.
// sigmoid(x) = 0.5*tanh(x/2)+0.5 (exact), tanh via MUFU.
// ============================================================================
#define LDA2 136
#define LDB2 72
__global__ __launch_bounds__(256, 2)
void k2_gates(const float* __restrict__ Wv, const float* __restrict__ bv,
              const float* __restrict__ Wu, const float* __restrict__ bu,
              const float* __restrict__ ww, const float* __restrict__ bw,
              const unsigned char* __restrict__ mask)
{
    __shared__ uint32_t As[2][8][LDA2];
    __shared__ uint32_t BV[2][8][LDB2];
    __shared__ uint32_t BU[2][8][LDB2];
    __shared__ float red[2][128];

    const int tid = threadIdx.x;
    const int lane = tid & 31, wid = tid >> 5;
    const int wm = wid & 3, wn = wid >> 2;    // warp: rows wm*32, cols wn*32
    const int g = lane >> 2, tg = lane & 3;
    const size_t m0 = (size_t)blockIdx.x * 128;

    const int am = tid >> 1, ak = (tid & 1) << 3;
    const int bk = (tid >> 5) << 1;          // k-rows bk, bk+1
    const int bn = (tid & 31) << 1;          // 2 n-values

    float rowsum[4] = {0.f, 0.f, 0.f, 0.f};

    for (int nb = 0; nb < 4; nb++) {
        const int n0 = nb * 64;
        float4 accV[2][4], accU[2][4];
        #pragma unroll
        for (int i = 0; i < 2; i++)
            #pragma unroll
            for (int j = 0; j < 4; j++) {
                accV[i][j] = make_float4(0.f, 0.f, 0.f, 0.f);
                accU[i][j] = make_float4(0.f, 0.f, 0.f, 0.f);
            }

        float4 ra0, ra1;
        float2 rv0, rv1, ru0, ru1;
        auto load_tile = [&](int kt) {
            const float* ap = &g_h[(m0 + am) * HH + kt * 16 + ak];
            ra0 = *(const float4*)(ap);  ra1 = *(const float4*)(ap + 4);
            const size_t bo = (size_t)(kt * 16 + bk) * HH + n0 + bn;
            rv0 = *(const float2*)(Wv + bo);
            rv1 = *(const float2*)(Wv + bo + HH);
            ru0 = *(const float2*)(Wu + bo);
            ru1 = *(const float2*)(Wu + bo + HH);
        };
        auto store_tile = [&](int p) {
            const int a2 = ak >> 1;
            As[p][a2 + 0][am] = pbf(ra0.x, ra0.y);
            As[p][a2 + 1][am] = pbf(ra0.z, ra0.w);
            As[p][a2 + 2][am] = pbf(ra1.x, ra1.y);
            As[p][a2 + 3][am] = pbf(ra1.z, ra1.w);
            *(uint2*)&BV[p][bk >> 1][bn] = make_uint2(pbf(rv0.x, rv1.x), pbf(rv0.y, rv1.y));
            *(uint2*)&BU[p][bk >> 1][bn] = make_uint2(pbf(ru0.x, ru1.x), pbf(ru0.y, ru1.y));
        };

        load_tile(0); store_tile(0);
        __syncthreads();

        for (int kt = 0; kt < 16; kt++) {
            const int p = kt & 1;
            if (kt + 1 < 16) load_tile(kt + 1);
            uint32_t afr[2][4];
            #pragma unroll
            for (int fm = 0; fm < 2; fm++) {
                const int m = wm * 32 + fm * 16 + g;
                afr[fm][0] = As[p][tg][m];     afr[fm][1] = As[p][tg][m + 8];
                afr[fm][2] = As[p][tg + 4][m]; afr[fm][3] = As[p][tg + 4][m + 8];
            }
            #pragma unroll
            for (int fn = 0; fn < 4; fn++) {
                const int n = wn * 32 + fn * 8 + g;
                const uint32_t v0 = BV[p][tg][n], v1 = BV[p][tg + 4][n];
                const uint32_t u0 = BU[p][tg][n], u1 = BU[p][tg + 4][n];
                mma16(accV[0][fn], afr[0], v0, v1);
                mma16(accV[1][fn], afr[1], v0, v1);
                mma16(accU[0][fn], afr[0], u0, u1);
                mma16(accU[1][fn], afr[1], u0, u1);
            }
            if (kt + 1 < 16) {
                store_tile(p ^ 1);
                __syncthreads();
            }
        }
        __syncthreads();   // safe to overwrite smem next nb

        #pragma unroll
        for (int fm = 0; fm < 2; fm++) {
            #pragma unroll
            for (int fn = 0; fn < 4; fn++) {
                const int c = n0 + wn * 32 + fn * 8 + tg * 2;
                const float bv0 = bv[c], bv1 = bv[c + 1];
                const float bu0 = bu[c], bu1 = bu[c + 1];
                const float w0 = ww[c],  w1 = ww[c + 1];
                const float4 av = accV[fm][fn], au = accU[fm][fn];
                float v, u;
                v = tanhfast(av.x + bv0); u = 0.5f * tanhfast(0.5f * (au.x + bu0)) + 0.5f;
                rowsum[fm * 2 + 0] = fmaf(v * u, w0, rowsum[fm * 2 + 0]);
                v = tanhfast(av.y + bv1); u = 0.5f * tanhfast(0.5f * (au.y + bu1)) + 0.5f;
                rowsum[fm * 2 + 0] = fmaf(v * u, w1, rowsum[fm * 2 + 0]);
                v = tanhfast(av.z + bv0); u = 0.5f * tanhfast(0.5f * (au.z + bu0)) + 0.5f;
                rowsum[fm * 2 + 1] = fmaf(v * u, w0, rowsum[fm * 2 + 1]);
                v = tanhfast(av.w + bv1); u = 0.5f * tanhfast(0.5f * (au.w + bu1)) + 0.5f;
                rowsum[fm * 2 + 1] = fmaf(v * u, w1, rowsum[fm * 2 + 1]);
            }
        }
    }

    #pragma unroll
    for (int o = 1; o <= 2; o <<= 1)
        #pragma unroll
        for (int i = 0; i < 4; i++)
            rowsum[i] += __shfl_xor_sync(0xffffffffu, rowsum[i], o);

    if (tg == 0) {
        #pragma unroll
        for (int i = 0; i < 4; i++)
            red[wn][wm * 32 + (i >> 1) * 16 + (i & 1) * 8 + g] = rowsum[i];
    }
    __syncthreads();
    if (tid < 128) {
        const size_t m = m0 + tid;
        float val = red[0][tid] + red[1][tid] + bw[0];
        if (mask[m]) val = -1e30f;
        g_logit[m] = val;
    }
}

// ============================================================================
// K3a: per-batch softmax stats. 8 CTAs x 1024 threads.
// ============================================================================
__global__ __launch_bounds__(1024)
void k3a_stats()
{
    __shared__ float sred[1024];
    const int b = blockIdx.x, tid = threadIdx.x;
    const float* lg = g_logit + (size_t)b * TT;

    float lmax = -FLT_MAX;
    #pragma unroll
    for (int i = 0; i < 8; i++) lmax = fmaxf(lmax, lg[tid + i * 1024]);
    sred[tid] = lmax;
    __syncthreads();
    for (int s = 512; s > 0; s >>= 1) {
        if (tid < s) sred[tid] = fmaxf(sred[tid], sred[tid + s]);
        __syncthreads();
    }
    const float mx = sred[0];
    __syncthreads();

    float lsum = 0.f;
    #pragma unroll
    for (int i = 0; i < 8; i++) lsum += expf(lg[tid + i * 1024] - mx);
    sred[tid] = lsum;
    __syncthreads();
    for (int s = 512; s > 0; s >>= 1) {
        if (tid < s) sred[tid] += sred[tid + s];
        __syncthreads();
    }
    if (tid == 0) g_stat[b] = make_float2(mx, 1.f / sred[0]);
}

// ============================================================================
// K3b: partial pooling. grid (NCHUNK=64 chunks, 8 batches) x 256; 128 tokens/chunk.
// ============================================================================
__global__ __launch_bounds__(256)
void k3b_pool()
{
    __shared__ float w[128];
    const int b = blockIdx.y, ch = blockIdx.x, tid = threadIdx.x;
    const float2 st = g_stat[b];
    const int t0 = ch * 128;

    if (tid < 128)
        w[tid] = expf(g_logit[(size_t)b * TT + t0 + tid] - st.x) * st.y;
    __syncthreads();

    const float* hp = &g_h[((size_t)b * TT + t0) * HH + tid];
    float a0 = 0.f, a1 = 0.f, a2 = 0.f, a3 = 0.f;
    #pragma unroll 4
    for (int t = 0; t < 128; t += 4) {
        a0 = fmaf(w[t + 0], hp[(size_t)(t + 0) * HH], a0);
        a1 = fmaf(w[t + 1], hp[(size_t)(t + 1) * HH], a1);
        a2 = fmaf(w[t + 2], hp[(size_t)(t + 2) * HH], a2);
        a3 = fmaf(w[t + 3], hp[(size_t)(t + 3) * HH], a3);
    }
    g_part[((size_t)b * NCHUNK + ch) * HH + tid] = (a0 + a1) + (a2 + a3);
}

// ============================================================================
// K3c: reduce NCHUNK partials -> slide. 8 CTAs x 256.
// ============================================================================
__global__ __launch_bounds__(256)
void k3c_reduce()
{
    const int b = blockIdx.x, c = threadIdx.x;
    float s = 0.f;
    #pragma unroll 8
    for (int j = 0; j < NCHUNK; j++) s += g_part[((size_t)b * NCHUNK + j) * HH + c];
    g_slide[b * HH + c] = s;
}

// ============================================================================
// K4: logits[b,o] = slide[b,:] @ Wc[:,o] + bc[o]
// ============================================================================
__global__ __launch_bounds__(512)
void k4_final(const float* __restrict__ Wc, const float* __restrict__ bc,
              float* __restrict__ out)
{
    const int tid = threadIdx.x;
    const int pair = tid >> 5, lane = tid & 31;
    const int b = pair >> 1, o = pair & 1;
    float s = 0.f;
    for (int j = lane; j < HH; j += 32)
        s = fmaf(g_slide[b * HH + j], Wc[j * OO + o], s);
    #pragma unroll
    for (int off = 16; off > 0; off >>= 1) s += __shfl_down_sync(0xffffffffu, s, off);
    if (lane == 0) out[b * OO + o] = s + bc[o];
}

// ============================================================================
extern "C" void kernel_launch(void* const* d_in, const int* in_sizes, int n_in,
                              void* d_out, int out_size)
{
    const float*         bags = (const float*)d_in[0];
    const unsigned char* mask = (const unsigned char*)d_in[1];
    const float*         W1   = (const float*)d_in[2];
    const float*         b1   = (const float*)d_in[3];
    const float*         Wv   = (const float*)d_in[4];
    const float*         bv   = (const float*)d_in[5];
    const float*         Wu   = (const float*)d_in[6];
    const float*         bu   = (const float*)d_in[7];
    const float*         ww   = (const float*)d_in[8];
    const float*         bw   = (const float*)d_in[9];
    const float*         Wc   = (const float*)d_in[10];
    const float*         bc   = (const float*)d_in[11];
    float*               out  = (float*)d_out;

    k1_gemm_relu<<<dim3(HH / 128, MTOK / 128), 256>>>(bags, W1, b1);
    k2_gates<<<MTOK / 128, 256>>>(Wv, bv, Wu, bu, ww, bw, mask);
    k3a_stats<<<BSZ, 1024>>>();
    k3b_pool<<<dim3(NCHUNK, BSZ), 256>>>();
    k3c_reduce<<<BSZ, 256>>>();
    k4_final<<<1, 512>>>(Wc, bc, out);
}

// round 7
// speedup vs baseline: 4.2745x; 1.0958x over previous
#include <cuda_runtime.h>
#include <math.h>
#include <stdint.h>
#include <float.h>

#define BSZ 8
#define TT  8192
#define FF  1024
#define HH  256
#define OO  2
#define MTOK (BSZ * TT)   // 65536 tokens
#define NCHUNK 64

// ---- scratch (static device globals; no runtime allocation) ----
__device__ float  g_h[(size_t)MTOK * HH];     // 64 MB fp32 h (for K3 pooling)
__device__ uint4  g_hb4[(size_t)MTOK * 32];   // 32 MB bf16x2-packed h (for K2 A)
__device__ float  g_logit[MTOK];
__device__ float2 g_stat[BSZ];
__device__ float  g_part[BSZ * NCHUNK * HH];
__device__ float  g_slide[BSZ * HH];
__device__ uint4  g_w1s[64 * 512];            // 512 KB: W1 bf16 stage images [kt][kp][n]
__device__ uint4  g_wvs[16 * 512];            // 128 KB: Wv bf16 stage images [nb*4+kh]
__device__ uint4  g_wus[16 * 512];            // 128 KB: Wu

// ---- helpers ----
__device__ __forceinline__ uint32_t pbf(float lo, float hi) {
    uint32_t r; asm("cvt.rn.bf16x2.f32 %0, %1, %2;" : "=r"(r) : "f"(hi), "f"(lo)); return r;
}
__device__ __forceinline__ float tanhfast(float x) {
    float y; asm("tanh.approx.f32 %0, %1;" : "=f"(y) : "f"(x)); return y;
}
__device__ __forceinline__ void mma16(float4& d, const uint32_t* a, uint32_t b0, uint32_t b1) {
    asm volatile("mma.sync.aligned.m16n8k16.row.col.f32.bf16.bf16.f32 "
        "{%0,%1,%2,%3}, {%4,%5,%6,%7}, {%8,%9}, {%0,%1,%2,%3};"
        : "+f"(d.x), "+f"(d.y), "+f"(d.z), "+f"(d.w)
        : "r"(a[0]), "r"(a[1]), "r"(a[2]), "r"(a[3]), "r"(b0), "r"(b1));
}

// ============================================================================
// k1pre: W1 [1024,256] fp32 -> bf16 stage images. Stage kt (64): 8 kpairs x 256 n.
// word layout within stage: kp*256 + n  (packed pair: W1[2kp][n], W1[2kp+1][n])
// ============================================================================
__global__ __launch_bounds__(256)
void k1pre(const float* __restrict__ W1)
{
    const int kt = blockIdx.x, tid = threadIdx.x;
    const int kp = tid >> 5, n8 = (tid & 31) << 3;
    const float* r0 = W1 + (size_t)(kt * 16 + 2 * kp) * HH + n8;
    const float4 a0 = *(const float4*)(r0),        a1 = *(const float4*)(r0 + 4);
    const float4 b0 = *(const float4*)(r0 + HH),   b1 = *(const float4*)(r0 + HH + 4);
    uint4 q0 = make_uint4(pbf(a0.x, b0.x), pbf(a0.y, b0.y), pbf(a0.z, b0.z), pbf(a0.w, b0.w));
    uint4 q1 = make_uint4(pbf(a1.x, b1.x), pbf(a1.y, b1.y), pbf(a1.z, b1.z), pbf(a1.w, b1.w));
    g_w1s[kt * 512 + kp * 64 + (n8 >> 2)]     = q0;
    g_w1s[kt * 512 + kp * 64 + (n8 >> 2) + 1] = q1;
}

// ============================================================================
// k2pre: Wv/Wu [256,256] fp32 -> bf16 stage images. Block blk = nb*4 + kh:
// 32 kpairs (k rows kh*64..+63) x 64 n (cols nb*64..+63). word: kp*64 + n.
// ============================================================================
__global__ __launch_bounds__(256)
void k2pre(const float* __restrict__ Wv, const float* __restrict__ Wu)
{
    const int blk = blockIdx.x, tid = threadIdx.x;
    const int nb = blk >> 2, kh = blk & 3;
    const int kp = tid >> 3, n8 = (tid & 7) << 3;
    const size_t off = (size_t)(kh * 64 + 2 * kp) * HH + nb * 64 + n8;
    {
        const float4 a0 = *(const float4*)(Wv + off),      a1 = *(const float4*)(Wv + off + 4);
        const float4 b0 = *(const float4*)(Wv + off + HH), b1 = *(const float4*)(Wv + off + HH + 4);
        g_wvs[blk * 512 + kp * 16 + (n8 >> 2)] =
            make_uint4(pbf(a0.x, b0.x), pbf(a0.y, b0.y), pbf(a0.z, b0.z), pbf(a0.w, b0.w));
        g_wvs[blk * 512 + kp * 16 + (n8 >> 2) + 1] =
            make_uint4(pbf(a1.x, b1.x), pbf(a1.y, b1.y), pbf(a1.z, b1.z), pbf(a1.w, b1.w));
    }
    {
        const float4 a0 = *(const float4*)(Wu + off),      a1 = *(const float4*)(Wu + off + 4);
        const float4 b0 = *(const float4*)(Wu + off + HH), b1 = *(const float4*)(Wu + off + HH + 4);
        g_wus[blk * 512 + kp * 16 + (n8 >> 2)] =
            make_uint4(pbf(a0.x, b0.x), pbf(a0.y, b0.y), pbf(a0.z, b0.z), pbf(a0.w, b0.w));
        g_wus[blk * 512 + kp * 16 + (n8 >> 2) + 1] =
            make_uint4(pbf(a1.x, b1.x), pbf(a1.y, b1.y), pbf(a1.z, b1.z), pbf(a1.w, b1.w));
    }
}

// ============================================================================
// K1: h = relu(bags @ W1 + b1). CTA 128x256 (full N), 512 threads, 16 warps
// (warp tile 32x64), bf16 m16n8k16, double-buffered K=16 stages.
// Writes fp32 h (K3) + packed bf16 h (K2).
// ============================================================================
#define LDA1 136
#define LDB1 264
__global__ __launch_bounds__(512, 1)
void k1_gemm_relu(const float* __restrict__ A, const float* __restrict__ bias)
{
    __shared__ uint32_t As[2][8][LDA1];   // [kpair][m]
    __shared__ uint32_t Bs[2][8][LDB1];   // [kpair][n]

    const int tid = threadIdx.x;
    const int lane = tid & 31, wid = tid >> 5;
    const int wm = wid & 3, wn = wid >> 2;       // warp: rows wm*32, cols wn*64
    const int g = lane >> 2, tg = lane & 3;
    const size_t mBase = (size_t)blockIdx.x * 128;

    const int am = tid >> 2, ak4 = (tid & 3) << 2;    // A: row, 4 k-values
    const int bkp = tid >> 6, bn4 = (tid & 63) << 2;  // B: kpair, 4 n-values
    const float* aP = A + (mBase + am) * FF + ak4;
    const uint4* bSrc = g_w1s + bkp * 64 + (bn4 >> 2);

    float4 acc[2][8];
    #pragma unroll
    for (int i = 0; i < 2; i++)
        #pragma unroll
        for (int j = 0; j < 8; j++) acc[i][j] = make_float4(0.f, 0.f, 0.f, 0.f);

    float4 ra;  uint4 rb;
    ra = *(const float4*)(aP);
    rb = bSrc[0];

    auto store_tile = [&](int p) {
        const int kp = ak4 >> 1;
        As[p][kp][am]     = pbf(ra.x, ra.y);
        As[p][kp + 1][am] = pbf(ra.z, ra.w);
        *(uint4*)&Bs[p][bkp][bn4] = rb;
    };

    store_tile(0);
    __syncthreads();

    for (int kt = 0; kt < 64; kt++) {
        const int p = kt & 1;
        if (kt + 1 < 64) {
            ra = *(const float4*)(aP + (kt + 1) * 16);
            rb = bSrc[(kt + 1) * 512];
        }
        uint32_t afr[2][4];
        #pragma unroll
        for (int fm = 0; fm < 2; fm++) {
            const int m = wm * 32 + fm * 16 + g;
            afr[fm][0] = As[p][tg][m];     afr[fm][1] = As[p][tg][m + 8];
            afr[fm][2] = As[p][tg + 4][m]; afr[fm][3] = As[p][tg + 4][m + 8];
        }
        #pragma unroll
        for (int fn = 0; fn < 8; fn++) {
            const int n = wn * 64 + fn * 8 + g;
            const uint32_t b0 = Bs[p][tg][n], b1 = Bs[p][tg + 4][n];
            mma16(acc[0][fn], afr[0], b0, b1);
            mma16(acc[1][fn], afr[1], b0, b1);
        }
        if (kt + 1 < 64) {
            store_tile(p ^ 1);
            __syncthreads();
        }
    }

    // epilogue: bias+relu -> fp32 h + packed bf16 h
    #pragma unroll
    for (int fm = 0; fm < 2; fm++) {
        #pragma unroll
        for (int half = 0; half < 2; half++) {        // acc rows g(+0) / g+8
            const size_t m = mBase + wm * 32 + fm * 16 + g + half * 8;
            float hv[16];
            #pragma unroll
            for (int fn = 0; fn < 8; fn++) {
                const int c = wn * 64 + fn * 8 + tg * 2;
                const float2 v = half == 0
                    ? make_float2(acc[fm][fn].x, acc[fm][fn].y)
                    : make_float2(acc[fm][fn].z, acc[fm][fn].w);
                hv[fn * 2 + 0] = fmaxf(v.x + bias[c], 0.f);
                hv[fn * 2 + 1] = fmaxf(v.y + bias[c + 1], 0.f);
                *(float2*)&g_h[m * HH + c] = make_float2(hv[fn * 2], hv[fn * 2 + 1]);
            }
            // pack: this thread owns cols {wn*64 + fn*8 + tg*2, +1} — pairs are
            // (even,odd) adjacent, so pack per-fn word and store 2 uint4 per 4 fn
            #pragma unroll
            for (int q = 0; q < 2; q++) {
                uint4 w;
                w.x = pbf(hv[q * 8 + 0], hv[q * 8 + 1]);
                w.y = pbf(hv[q * 8 + 2], hv[q * 8 + 3]);
                w.z = pbf(hv[q * 8 + 4], hv[q * 8 + 5]);
                w.w = pbf(hv[q * 8 + 6], hv[q * 8 + 7]);
                // words cover cols wn*64 + (q*4..q*4+3)*8 + tg*2 — NOT contiguous!
                // store as 4 scalar words instead:
                uint32_t* dst = (uint32_t*)g_hb4 + m * 128;
                dst[(wn * 64 + (q * 4 + 0) * 8 + tg * 2) >> 1] = w.x;
                dst[(wn * 64 + (q * 4 + 1) * 8 + tg * 2) >> 1] = w.y;
                dst[(wn * 64 + (q * 4 + 2) * 8 + tg * 2) >> 1] = w.z;
                dst[(wn * 64 + (q * 4 + 3) * 8 + tg * 2) >> 1] = w.w;
            }
        }
    }
}

// ============================================================================
// K2: gated-attention logits. A (h tile, 128x256 bf16) resident in smem for
// all 4 n-blocks; B staged per (nb, khalf) as pure uint4 copies of bf16 images.
// ============================================================================
#define LDA2 136
#define LDB2 72
extern __shared__ uint32_t k2smem[];
__global__ __launch_bounds__(256, 2)
void k2_gates(const float* __restrict__ bv, const float* __restrict__ bu,
              const float* __restrict__ ww, const float* __restrict__ bw,
              const unsigned char* __restrict__ mask)
{
    uint32_t* As = k2smem;                 // [128 kpair][LDA2] -> 128*136
    uint32_t* BVs = As + 128 * LDA2;       // [32 kpair][LDB2]
    uint32_t* BUs = BVs + 32 * LDB2;
    __shared__ float red[2][128];

    const int tid = threadIdx.x;
    const int lane = tid & 31, wid = tid >> 5;
    const int wm = wid & 3, wn = wid >> 2;       // warp: rows wm*32, cols wn*32
    const int g = lane >> 2, tg = lane & 3;
    const size_t m0 = (size_t)blockIdx.x * 128;

    // ---- stage A once: pure copy of packed bf16 h ----
    {
        const int am = tid >> 1, khalf = tid & 1;
        const uint4* src = g_hb4 + (m0 + am) * 32 + khalf * 16;
        #pragma unroll
        for (int jj = 0; jj < 16; jj++) {
            const uint4 v = src[jj];
            const int kp = khalf * 64 + jj * 4;
            As[(kp + 0) * LDA2 + am] = v.x;
            As[(kp + 1) * LDA2 + am] = v.y;
            As[(kp + 2) * LDA2 + am] = v.z;
            As[(kp + 3) * LDA2 + am] = v.w;
        }
    }
    __syncthreads();

    float rowsum[4] = {0.f, 0.f, 0.f, 0.f};

    for (int nb = 0; nb < 4; nb++) {
        float4 accV[2][4], accU[2][4];
        #pragma unroll
        for (int i = 0; i < 2; i++)
            #pragma unroll
            for (int j = 0; j < 4; j++) {
                accV[i][j] = make_float4(0.f, 0.f, 0.f, 0.f);
                accU[i][j] = make_float4(0.f, 0.f, 0.f, 0.f);
            }

        for (int kh = 0; kh < 4; kh++) {
            // ---- stage B: 2 uint4 per matrix per thread ----
            {
                const int blk = nb * 4 + kh;
                const int w0 = tid * 8;                 // first word of 8
                const int kp = w0 >> 6, n8 = w0 & 63;
                const uint4 v0 = g_wvs[blk * 512 + tid * 2];
                const uint4 v1 = g_wvs[blk * 512 + tid * 2 + 1];
                const uint4 u0 = g_wus[blk * 512 + tid * 2];
                const uint4 u1 = g_wus[blk * 512 + tid * 2 + 1];
                *(uint4*)&BVs[kp * LDB2 + n8]     = v0;
                *(uint4*)&BVs[kp * LDB2 + n8 + 4] = v1;
                *(uint4*)&BUs[kp * LDB2 + n8]     = u0;
                *(uint4*)&BUs[kp * LDB2 + n8 + 4] = u1;
            }
            __syncthreads();

            #pragma unroll
            for (int kt = 0; kt < 4; kt++) {
                uint32_t afr[2][4];
                const int kr = kh * 32 + kt * 8;
                #pragma unroll
                for (int fm = 0; fm < 2; fm++) {
                    const int m = wm * 32 + fm * 16 + g;
                    afr[fm][0] = As[(kr + tg) * LDA2 + m];
                    afr[fm][1] = As[(kr + tg) * LDA2 + m + 8];
                    afr[fm][2] = As[(kr + tg + 4) * LDA2 + m];
                    afr[fm][3] = As[(kr + tg + 4) * LDA2 + m + 8];
                }
                #pragma unroll
                for (int fn = 0; fn < 4; fn++) {
                    const int n = wn * 32 + fn * 8 + g;
                    const int r0 = kt * 8 + tg, r1 = kt * 8 + tg + 4;
                    const uint32_t v0 = BVs[r0 * LDB2 + n], v1 = BVs[r1 * LDB2 + n];
                    const uint32_t u0 = BUs[r0 * LDB2 + n], u1 = BUs[r1 * LDB2 + n];
                    mma16(accV[0][fn], afr[0], v0, v1);
                    mma16(accV[1][fn], afr[1], v0, v1);
                    mma16(accU[0][fn], afr[0], u0, u1);
                    mma16(accU[1][fn], afr[1], u0, u1);
                }
            }
            __syncthreads();   // stage reads done before next overwrite
        }

        const int n0 = nb * 64;
        #pragma unroll
        for (int fm = 0; fm < 2; fm++) {
            #pragma unroll
            for (int fn = 0; fn < 4; fn++) {
                const int c = n0 + wn * 32 + fn * 8 + tg * 2;
                const float bv0 = bv[c], bv1 = bv[c + 1];
                const float bu0 = bu[c], bu1 = bu[c + 1];
                const float w0 = ww[c],  w1 = ww[c + 1];
                const float4 av = accV[fm][fn], au = accU[fm][fn];
                float v, u;
                v = tanhfast(av.x + bv0); u = 0.5f * tanhfast(0.5f * (au.x + bu0)) + 0.5f;
                rowsum[fm * 2 + 0] = fmaf(v * u, w0, rowsum[fm * 2 + 0]);
                v = tanhfast(av.y + bv1); u = 0.5f * tanhfast(0.5f * (au.y + bu1)) + 0.5f;
                rowsum[fm * 2 + 0] = fmaf(v * u, w1, rowsum[fm * 2 + 0]);
                v = tanhfast(av.z + bv0); u = 0.5f * tanhfast(0.5f * (au.z + bu0)) + 0.5f;
                rowsum[fm * 2 + 1] = fmaf(v * u, w0, rowsum[fm * 2 + 1]);
                v = tanhfast(av.w + bv1); u = 0.5f * tanhfast(0.5f * (au.w + bu1)) + 0.5f;
                rowsum[fm * 2 + 1] = fmaf(v * u, w1, rowsum[fm * 2 + 1]);
            }
        }
    }

    #pragma unroll
    for (int o = 1; o <= 2; o <<= 1)
        #pragma unroll
        for (int i = 0; i < 4; i++)
            rowsum[i] += __shfl_xor_sync(0xffffffffu, rowsum[i], o);

    if (tg == 0) {
        #pragma unroll
        for (int i = 0; i < 4; i++)
            red[wn][wm * 32 + (i >> 1) * 16 + (i & 1) * 8 + g] = rowsum[i];
    }
    __syncthreads();
    if (tid < 128) {
        const size_t m = m0 + tid;
        float val = red[0][tid] + red[1][tid] + bw[0];
        if (mask[m]) val = -1e30f;
        g_logit[m] = val;
    }
}

// ============================================================================
// K3a/b/c + K4
// ============================================================================
__global__ __launch_bounds__(1024)
void k3a_stats()
{
    __shared__ float sred[1024];
    const int b = blockIdx.x, tid = threadIdx.x;
    const float* lg = g_logit + (size_t)b * TT;

    float lmax = -FLT_MAX;
    #pragma unroll
    for (int i = 0; i < 8; i++) lmax = fmaxf(lmax, lg[tid + i * 1024]);
    sred[tid] = lmax;
    __syncthreads();
    for (int s = 512; s > 0; s >>= 1) {
        if (tid < s) sred[tid] = fmaxf(sred[tid], sred[tid + s]);
        __syncthreads();
    }
    const float mx = sred[0];
    __syncthreads();

    float lsum = 0.f;
    #pragma unroll
    for (int i = 0; i < 8; i++) lsum += __expf(lg[tid + i * 1024] - mx);
    sred[tid] = lsum;
    __syncthreads();
    for (int s = 512; s > 0; s >>= 1) {
        if (tid < s) sred[tid] += sred[tid + s];
        __syncthreads();
    }
    if (tid == 0) g_stat[b] = make_float2(mx, 1.f / sred[0]);
}

__global__ __launch_bounds__(256)
void k3b_pool()
{
    __shared__ float w[128];
    const int b = blockIdx.y, ch = blockIdx.x, tid = threadIdx.x;
    const float2 st = g_stat[b];
    const int t0 = ch * 128;

    if (tid < 128)
        w[tid] = __expf(g_logit[(size_t)b * TT + t0 + tid] - st.x) * st.y;
    __syncthreads();

    const float* hp = &g_h[((size_t)b * TT + t0) * HH + tid];
    float a0 = 0.f, a1 = 0.f, a2 = 0.f, a3 = 0.f;
    #pragma unroll 4
    for (int t = 0; t < 128; t += 4) {
        a0 = fmaf(w[t + 0], hp[(size_t)(t + 0) * HH], a0);
        a1 = fmaf(w[t + 1], hp[(size_t)(t + 1) * HH], a1);
        a2 = fmaf(w[t + 2], hp[(size_t)(t + 2) * HH], a2);
        a3 = fmaf(w[t + 3], hp[(size_t)(t + 3) * HH], a3);
    }
    g_part[((size_t)b * NCHUNK + ch) * HH + tid] = (a0 + a1) + (a2 + a3);
}

__global__ __launch_bounds__(256)
void k3c_reduce()
{
    const int b = blockIdx.x, c = threadIdx.x;
    float s = 0.f;
    #pragma unroll 8
    for (int j = 0; j < NCHUNK; j++) s += g_part[((size_t)b * NCHUNK + j) * HH + c];
    g_slide[b * HH + c] = s;
}

__global__ __launch_bounds__(512)
void k4_final(const float* __restrict__ Wc, const float* __restrict__ bc,
              float* __restrict__ out)
{
    const int tid = threadIdx.x;
    const int pair = tid >> 5, lane = tid & 31;
    const int b = pair >> 1, o = pair & 1;
    float s = 0.f;
    for (int j = lane; j < HH; j += 32)
        s = fmaf(g_slide[b * HH + j], Wc[j * OO + o], s);
    #pragma unroll
    for (int off = 16; off > 0; off >>= 1) s += __shfl_down_sync(0xffffffffu, s, off);
    if (lane == 0) out[b * OO + o] = s + bc[o];
}

// ============================================================================
extern "C" void kernel_launch(void* const* d_in, const int* in_sizes, int n_in,
                              void* d_out, int out_size)
{
    const float*         bags = (const float*)d_in[0];
    const unsigned char* mask = (const unsigned char*)d_in[1];
    const float*         W1   = (const float*)d_in[2];
    const float*         b1   = (const float*)d_in[3];
    const float*         Wv   = (const float*)d_in[4];
    const float*         bv   = (const float*)d_in[5];
    const float*         Wu   = (const float*)d_in[6];
    const float*         bu   = (const float*)d_in[7];
    const float*         ww   = (const float*)d_in[8];
    const float*         bw   = (const float*)d_in[9];
    const float*         Wc   = (const float*)d_in[10];
    const float*         bc   = (const float*)d_in[11];
    float*               out  = (float*)d_out;

    const int k2_smem = (128 * LDA2 + 2 * 32 * LDB2) * 4;   // 88064 B
    cudaFuncSetAttribute(k2_gates, cudaFuncAttributeMaxDynamicSharedMemorySize, k2_smem);

    k1pre<<<64, 256>>>(W1);
    k2pre<<<16, 256>>>(Wv, Wu);
    k1_gemm_relu<<<MTOK / 128, 512>>>(bags, b1);
    k2_gates<<<MTOK / 128, 256, k2_smem>>>(bv, bu, ww, bw, mask);
    k3a_stats<<<BSZ, 1024>>>();
    k3b_pool<<<dim3(NCHUNK, BSZ), 256>>>();
    k3c_reduce<<<BSZ, 256>>>();
    k4_final<<<1, 512>>>(Wc, bc, out);
}